// round 3
// baseline (speedup 1.0000x reference)
#include <cuda_runtime.h>
#include <cstdint>

// Problem dims (fixed for this problem instance)
#define ZD 16
#define YD 384
#define XD 384
#define ZP 18        // padded z (zero slice at 0 and 17)
#define YP 386       // padded y
#define XGW 96       // XD/4 code words per row
#define NWIN_I 17    // z-pairs
#define NWIN_Y 385   // window rows
#define NGX 25       // 16-window groups per row (last group: only window x=384)
#define TOTAL_B_THREADS (NWIN_I * NWIN_Y * NGX)          // 163625
#define B_BLOCKS ((TOTAL_B_THREADS + 255) / 256)          // 640
#define NP_WIN 148225.0                                   // 385*385

// Scratch (static __device__ — zero-initialized, no allocation).
// Padded halo regions of g_D / g_C are NEVER written (stay 0 from init).
__device__ float    g_D[ZP * YP * XD];
__device__ unsigned g_C[ZP * YP * XGW];
__device__ float    g_part[3 * B_BLOCKS];
__device__ unsigned g_count;

// ---------------------------------------------------------------------------
// kA: per-voxel precompute over the VALID region only. 4 voxels per thread.
// Also resets the last-block counter for kB.
__global__ void kA(const float* __restrict__ pred, const int* __restrict__ lab) {
    int w = blockIdx.x * blockDim.x + threadIdx.x;
    if (w == 0) g_count = 0u;
    const int W = ZD * YD * XGW;   // 589824
    if (w >= W) return;
    int xg = w % XGW;
    int rem = w / XGW;
    int y = rem % YD;
    int z = rem / YD;

    int x0 = xg * 4;
    const float4 p4 = *reinterpret_cast<const float4*>(pred + ((z * YD + y) * XD + x0));
    const int4   l4 = *reinterpret_cast<const int4*>(lab + ((z * YD + y) * XD + x0));

    float s0 = __fdividef(1.f, 1.f + __expf(-p4.x));
    float s1 = __fdividef(1.f, 1.f + __expf(-p4.y));
    float s2 = __fdividef(1.f, 1.f + __expf(-p4.z));
    float s3 = __fdividef(1.f, 1.f + __expf(-p4.w));

    float f0 = (float)l4.x, f1 = (float)l4.y, f2 = (float)l4.z, f3 = (float)l4.w;
    float4 d4;
    d4.x = (s0 - f0) * (s0 - f0);
    d4.y = (s1 - f1) * (s1 - f1);
    d4.z = (s2 - f2) * (s2 - f2);
    d4.w = (s3 - f3) * (s3 - f3);

    unsigned b0 = (unsigned)(l4.x & 1) | (p4.x > 0.f ? 0x10u : 0u);
    unsigned b1 = (unsigned)(l4.y & 1) | (p4.y > 0.f ? 0x10u : 0u);
    unsigned b2 = (unsigned)(l4.z & 1) | (p4.z > 0.f ? 0x10u : 0u);
    unsigned b3 = (unsigned)(l4.w & 1) | (p4.w > 0.f ? 0x10u : 0u);
    unsigned code = b0 | (b1 << 8) | (b2 << 16) | (b3 << 24);

    int zp = z + 1, yp = y + 1;
    int base = (zp * YP + yp) * XD + x0;
    *reinterpret_cast<float4*>(g_D + base) = d4;
    g_C[(zp * YP + yp) * XGW + xg] = code;
}

// ---------------------------------------------------------------------------
// Rare-path BCE: byte==0 -> softplus(p), byte==255 -> softplus(-p).
__device__ __noinline__ float bce8(const float* __restrict__ pred, int i, int yw, int x, bool ones) {
    float s = 0.f;
#pragma unroll
    for (int dz = 0; dz < 2; dz++)
#pragma unroll
        for (int dy = 0; dy < 2; dy++)
#pragma unroll
            for (int dx = 0; dx < 2; dx++) {
                int z = i - 1 + dz, y = yw - 1 + dy, xv = x - 1 + dx;
                if (z >= 0 && z < ZD && y >= 0 && y < YD && xv >= 0 && xv < XD) {
                    float p = __ldg(&pred[(z * YD + y) * XD + xv]);
                    float u = ones ? -p : p;
                    s += fmaxf(u, 0.f) + __logf(1.f + __expf(-fabsf(u)));
                }
            }
    return s;
}

__device__ __forceinline__ unsigned wsel(uint4 u, int j) {
    return j == 0 ? u.x : (j == 1 ? u.y : (j == 2 ? u.z : u.w));
}

__device__ __forceinline__ float warp_sum(float v) {
#pragma unroll
    for (int off = 16; off > 0; off >>= 1)
        v += __shfl_down_sync(0xffffffffu, v, off);
    return v;
}

// ---------------------------------------------------------------------------
// kB: each thread sweeps 16 consecutive windows along x for a fixed (i, yw).
// Last block to finish also does the final reduce and writes the scalar out.
__global__ void kB(const float* __restrict__ pred, const float* __restrict__ area,
                   float* __restrict__ out) {
    __shared__ float a_sh[256];
    __shared__ float wN[8], wD[8], wB[8];
    __shared__ bool is_last;
    int tid = threadIdx.x;

    // build permuted area LUT in-place: index = (c_prev4<<4)|c_new4
    {
        int a = tid >> 4, b = tid & 15;
        int byte = 0;
#pragma unroll
        for (int m = 0; m < 4; m++) {
            byte |= ((a >> m) & 1) << (2 * m);
            byte |= ((b >> m) & 1) << (2 * m + 1);
        }
        a_sh[tid] = __ldg(&area[byte]);
    }
    __syncthreads();

    float accN = 0.f, accD = 0.f, accB = 0.f;
    int t = blockIdx.x * 256 + tid;
    if (t < TOTAL_B_THREADS) {
        int g = t % NGX;
        int rem = t / NGX;
        int yw = rem % NWIN_Y;
        int i = rem / NWIN_Y;
        int x0 = g * 16;

        int rb0 = ((i + 0) * YP + (yw + 0)) * XD;
        int rb1 = ((i + 0) * YP + (yw + 1)) * XD;
        int rb2 = ((i + 1) * YP + (yw + 0)) * XD;
        int rb3 = ((i + 1) * YP + (yw + 1)) * XD;
        const unsigned char* C8 = reinterpret_cast<const unsigned char*>(g_C);

        float colDp;
        unsigned ccp;
        if (x0 == 0) {
            colDp = 0.f;
            ccp = 0u;
        } else {
            int c = x0 - 1;
            colDp = (g_D[rb0 + c] + g_D[rb1 + c]) + (g_D[rb2 + c] + g_D[rb3 + c]);
            unsigned b0 = C8[rb0 + c], b1 = C8[rb1 + c], b2 = C8[rb2 + c], b3 = C8[rb3 + c];
            ccp = (b0 & 0x11u) | ((b1 & 0x11u) << 1) | ((b2 & 0x11u) << 2) | ((b3 & 0x11u) << 3);
        }

        uint4 u0, u1, u2, u3;
        if (x0 < XD) {
            u0 = *reinterpret_cast<const uint4*>(C8 + rb0 + x0);
            u1 = *reinterpret_cast<const uint4*>(C8 + rb1 + x0);
            u2 = *reinterpret_cast<const uint4*>(C8 + rb2 + x0);
            u3 = *reinterpret_cast<const uint4*>(C8 + rb3 + x0);
        } else {
            u0 = u1 = u2 = u3 = make_uint4(0, 0, 0, 0);
        }

#pragma unroll
        for (int j = 0; j < 4; j++) {
            int c0 = x0 + 4 * j;
            float4 d0, d1, d2, d3;
            unsigned w0, w1, w2, w3;
            if (c0 < XD) {
                d0 = *reinterpret_cast<const float4*>(g_D + rb0 + c0);
                d1 = *reinterpret_cast<const float4*>(g_D + rb1 + c0);
                d2 = *reinterpret_cast<const float4*>(g_D + rb2 + c0);
                d3 = *reinterpret_cast<const float4*>(g_D + rb3 + c0);
                w0 = wsel(u0, j); w1 = wsel(u1, j); w2 = wsel(u2, j); w3 = wsel(u3, j);
            } else {
                d0 = d1 = d2 = d3 = make_float4(0.f, 0.f, 0.f, 0.f);
                w0 = w1 = w2 = w3 = 0u;
            }
            const unsigned M = 0x11111111u;
            unsigned tt = (w0 & M) | ((w1 & M) << 1) | ((w2 & M) << 2) | ((w3 & M) << 3);

            float cd0 = (d0.x + d1.x) + (d2.x + d3.x);
            float cd1 = (d0.y + d1.y) + (d2.y + d3.y);
            float cd2 = (d0.z + d1.z) + (d2.z + d3.z);
            float cd3 = (d0.w + d1.w) + (d2.w + d3.w);
            float cd[4] = {cd0, cd1, cd2, cd3};

#pragma unroll
            for (int k = 0; k < 4; k++) {
                int x = c0 + k;
                if (x <= 384) {
                    unsigned cc = __byte_perm(tt, 0u, 0x4440u | (unsigned)k);
                    float cdk = cd[k];
                    float q = colDp + cdk;
                    unsigned lidx = ((ccp << 4) & 0xF0u) | (cc & 0x0Fu);
                    unsigned pidx = (ccp & 0xF0u) | (cc >> 4);
                    float la = a_sh[lidx];
                    float pa = a_sh[pidx];
                    float pw = fmaf(q, -0.125f, 1.0f);
                    accN = fmaf(pw, la, accN);
                    accD += la + pa;
                    if (lidx == 0u || lidx == 255u) {
                        accB += bce8(pred, i, yw, x, lidx == 255u);
                    }
                    colDp = cdk;
                    ccp = cc;
                }
            }
        }
    }

    // deterministic warp-shuffle reduction
    accN = warp_sum(accN);
    accD = warp_sum(accD);
    accB = warp_sum(accB);
    int lane = tid & 31, warp = tid >> 5;
    if (lane == 0) { wN[warp] = accN; wD[warp] = accD; wB[warp] = accB; }
    __syncthreads();
    if (warp == 0) {
        float vN = lane < 8 ? wN[lane] : 0.f;
        float vD = lane < 8 ? wD[lane] : 0.f;
        float vB = lane < 8 ? wB[lane] : 0.f;
#pragma unroll
        for (int off = 4; off > 0; off >>= 1) {
            vN += __shfl_down_sync(0xffffffffu, vN, off);
            vD += __shfl_down_sync(0xffffffffu, vD, off);
            vB += __shfl_down_sync(0xffffffffu, vB, off);
        }
        if (lane == 0) {
            g_part[3 * blockIdx.x + 0] = vN;
            g_part[3 * blockIdx.x + 1] = vD;
            g_part[3 * blockIdx.x + 2] = vB;
        }
    }

    // last-block final reduction
    __threadfence();
    if (tid == 0) {
        unsigned prev = atomicAdd(&g_count, 1u);
        is_last = (prev == B_BLOCKS - 1);
    }
    __syncthreads();
    if (!is_last) return;

    double sN = 0.0, sD = 0.0, sB = 0.0;
    for (int b = tid; b < B_BLOCKS; b += 256) {
        sN += (double)g_part[3 * b + 0];
        sD += (double)g_part[3 * b + 1];
        sB += (double)g_part[3 * b + 2];
    }
    // reduce doubles via shared (reuse a_sh as 128 doubles? sizes: need 3x; do sequentially)
    __shared__ double rd[256];
    rd[tid] = sN; __syncthreads();
    for (int s = 128; s > 0; s >>= 1) { if (tid < s) rd[tid] += rd[tid + s]; __syncthreads(); }
    double tN = rd[0]; __syncthreads();
    rd[tid] = sD; __syncthreads();
    for (int s = 128; s > 0; s >>= 1) { if (tid < s) rd[tid] += rd[tid + s]; __syncthreads(); }
    double tD = rd[0]; __syncthreads();
    rd[tid] = sB; __syncthreads();
    for (int s = 128; s > 0; s >>= 1) { if (tid < s) rd[tid] += rd[tid + s]; __syncthreads(); }
    double tB = rd[0];

    if (tid == 0) {
        double dice = 1.0 - (2.0 * tN + 1e-3) / (tD + 1e-3);
        double vol = tB / (8.0 * NP_WIN);
        out[0] = (float)(dice + vol);
    }
}

// ---------------------------------------------------------------------------
extern "C" void kernel_launch(void* const* d_in, const int* in_sizes, int n_in,
                              void* d_out, int out_size) {
    const float* pred   = (const float*)d_in[0];
    const int*   labels = (const int*)d_in[1];
    const float* area   = (const float*)d_in[2];

    const int W = ZD * YD * XGW;
    kA<<<(W + 255) / 256, 256>>>(pred, labels);
    kB<<<B_BLOCKS, 256>>>(pred, area, (float*)d_out);
}

// round 4
// speedup vs baseline: 1.0436x; 1.0436x over previous
#include <cuda_runtime.h>
#include <cstdint>

// Problem dims (fixed)
#define ZD 16
#define YD 384
#define XD 384
#define YP 386        // padded y rows in E/ZC (row 0 and 385 stay zero)
#define NWIN_I 17     // z-pairs
#define NWIN_Y 385    // window rows
#define NGX 25        // 16-window groups per row (last group: only window x=384)
#define TOTAL_B_THREADS (NWIN_I * NWIN_Y * NGX)          // 163625
#define B_BLOCKS ((TOTAL_B_THREADS + 255) / 256)          // 640
#define NP_WIN 148225.0                                   // 385*385
#define SLAB (YD * XD)                                    // 147456

// Scratch (static __device__ — zero-initialized; padded rows never written)
__device__ float         g_E[NWIN_I * YP * XD];   // z-pair sums of (s-l)^2
__device__ unsigned char g_ZC[NWIN_I * YP * XD];  // z-pair code: l0@0,l1@2,p0@4,p1@6
__device__ float         g_part[3 * B_BLOCKS];
__device__ unsigned      g_count;

// ---------------------------------------------------------------------------
// k1: z-pass. One thread per (y,x) column; walks z, emits 17 z-pair sums+codes.
__global__ void k1(const float* __restrict__ pred, const int* __restrict__ lab) {
    int x = threadIdx.x;
    int y = blockIdx.x;
    if (x == 0 && y == 0) g_count = 0u;
    int base = y * XD + x;
    int obase = (y + 1) * XD + x;   // padded row index

    float dprev = 0.f;
    unsigned cprev = 0u;
#pragma unroll 4
    for (int z = 0; z < ZD; z++) {
        float p = __ldg(&pred[z * SLAB + base]);
        int   l = __ldg(&lab[z * SLAB + base]);
        float s = __fdividef(1.f, 1.f + __expf(-p));
        float f = (float)l;
        float d = (s - f) * (s - f);
        unsigned c = (unsigned)(l & 1) | (p > 0.f ? 0x10u : 0u);  // lab@0, pred@4
        // z-pair byte: lower z at bits 0/4, upper z at bits 2/6
        g_E[z * (YP * XD) + obase]  = dprev + d;
        g_ZC[z * (YP * XD) + obase] = (unsigned char)(cprev | (c << 2));
        dprev = d;
        cprev = c;
    }
    // last z-pair (i=16): upper slice is zero pad
    g_E[ZD * (YP * XD) + obase]  = dprev;
    g_ZC[ZD * (YP * XD) + obase] = (unsigned char)cprev;
}

// ---------------------------------------------------------------------------
// Rare-path BCE: byte==0 -> softplus(p), byte==255 -> softplus(-p).
__device__ __noinline__ float bce8(const float* __restrict__ pred, int i, int yw, int x, bool ones) {
    float s = 0.f;
#pragma unroll
    for (int dz = 0; dz < 2; dz++)
#pragma unroll
        for (int dy = 0; dy < 2; dy++)
#pragma unroll
            for (int dx = 0; dx < 2; dx++) {
                int z = i - 1 + dz, y = yw - 1 + dy, xv = x - 1 + dx;
                if (z >= 0 && z < ZD && y >= 0 && y < YD && xv >= 0 && xv < XD) {
                    float p = __ldg(&pred[(z * YD + y) * XD + xv]);
                    float u = ones ? -p : p;
                    s += fmaxf(u, 0.f) + __logf(1.f + __expf(-fabsf(u)));
                }
            }
    return s;
}

__device__ __forceinline__ unsigned wsel(uint4 u, int j) {
    return j == 0 ? u.x : (j == 1 ? u.y : (j == 2 ? u.z : u.w));
}

__device__ __forceinline__ float warp_sum(float v) {
#pragma unroll
    for (int off = 16; off > 0; off >>= 1)
        v += __shfl_down_sync(0xffffffffu, v, off);
    return v;
}

// ---------------------------------------------------------------------------
// k2: each thread sweeps 16 consecutive windows along x for a fixed (i, yw).
// Column sum F = E[rowA]+E[rowB]; column code cb = zcA | zcB<<1.
// Last block to finish does the final reduce and writes the scalar.
__global__ void k2(const float* __restrict__ pred, const float* __restrict__ area,
                   float* __restrict__ out) {
    __shared__ float a_sh[256];
    __shared__ float wN[8], wD[8], wB[8];
    __shared__ bool is_last;
    int tid = threadIdx.x;

    // permuted area LUT: index = (leftcol_nibble<<4)|rightcol_nibble,
    // nibble bit m = dz*2+dy -> true byte bit 2m+dx (left dx=0, right dx=1)
    {
        int a = tid >> 4, b = tid & 15;
        int byte = 0;
#pragma unroll
        for (int m = 0; m < 4; m++) {
            byte |= ((a >> m) & 1) << (2 * m);
            byte |= ((b >> m) & 1) << (2 * m + 1);
        }
        a_sh[tid] = __ldg(&area[byte]);
    }
    __syncthreads();

    float accN = 0.f, accLa = 0.f, accPa = 0.f, accB = 0.f;
    int t = blockIdx.x * 256 + tid;
    if (t < TOTAL_B_THREADS) {
        int g = t % NGX;
        int rem = t / NGX;
        int yw = rem % NWIN_Y;
        int i = rem / NWIN_Y;
        int x0 = g * 16;

        // padded rows: dy=0 -> row yw, dy=1 -> row yw+1
        int rA = (i * YP + yw) * XD;
        int rB = rA + XD;

        float Fp;
        unsigned cbp;
        if (x0 == 0) {
            Fp = 0.f;
            cbp = 0u;
        } else {
            int c = x0 - 1;
            Fp = g_E[rA + c] + g_E[rB + c];
            cbp = (unsigned)g_ZC[rA + c] | ((unsigned)g_ZC[rB + c] << 1);
        }

        float4 eA0, eA1, eA2, eA3, eB0, eB1, eB2, eB3;
        uint4 zA, zB;
        if (x0 < XD) {
            const float4* pA = reinterpret_cast<const float4*>(g_E + rA + x0);
            const float4* pB = reinterpret_cast<const float4*>(g_E + rB + x0);
            eA0 = pA[0]; eA1 = pA[1]; eA2 = pA[2]; eA3 = pA[3];
            eB0 = pB[0]; eB1 = pB[1]; eB2 = pB[2]; eB3 = pB[3];
            zA = *reinterpret_cast<const uint4*>(g_ZC + rA + x0);
            zB = *reinterpret_cast<const uint4*>(g_ZC + rB + x0);
        } else {
            eA0 = eA1 = eA2 = eA3 = make_float4(0.f, 0.f, 0.f, 0.f);
            eB0 = eB1 = eB2 = eB3 = eA0;
            zA = zB = make_uint4(0, 0, 0, 0);
        }

#pragma unroll
        for (int j = 0; j < 4; j++) {
            float4 ea = j == 0 ? eA0 : (j == 1 ? eA1 : (j == 2 ? eA2 : eA3));
            float4 eb = j == 0 ? eB0 : (j == 1 ? eB1 : (j == 2 ? eB2 : eB3));
            // column codes for 4 columns: zc bytes <= 0x55, so <<1 can't cross lanes
            unsigned cw = wsel(zA, j) | (wsel(zB, j) << 1);
            float F0 = ea.x + eb.x;
            float F1 = ea.y + eb.y;
            float F2 = ea.z + eb.z;
            float F3 = ea.w + eb.w;
            float Fv[4] = {F0, F1, F2, F3};

#pragma unroll
            for (int k = 0; k < 4; k++) {
                int x = x0 + 4 * j + k;        // window index
                if (x <= 384) {                // only false in last group
                    unsigned cb = __byte_perm(cw, 0u, 0x4440u | (unsigned)k);
                    float Fc = Fv[k];
                    float q = Fp + Fc;
                    unsigned lidx = ((cbp << 4) & 0xF0u) | (cb & 0x0Fu);
                    unsigned pidx = (cbp & 0xF0u) | (cb >> 4);
                    float la = a_sh[lidx];
                    float pa = a_sh[pidx];
                    float pw = fmaf(q, -0.125f, 1.0f);
                    accN = fmaf(pw, la, accN);
                    accLa += la;
                    accPa += pa;
                    if (((lidx + 1u) & 0xFFu) < 2u) {   // lidx==0 || lidx==255
                        accB += bce8(pred, i, yw, x, lidx == 255u);
                    }
                    Fp = Fc;
                    cbp = cb;
                }
            }
        }
    }
    float accD = accLa + accPa;

    // deterministic warp-shuffle reduction
    accN = warp_sum(accN);
    accD = warp_sum(accD);
    accB = warp_sum(accB);
    int lane = tid & 31, warp = tid >> 5;
    if (lane == 0) { wN[warp] = accN; wD[warp] = accD; wB[warp] = accB; }
    __syncthreads();
    if (warp == 0) {
        float vN = lane < 8 ? wN[lane] : 0.f;
        float vD = lane < 8 ? wD[lane] : 0.f;
        float vB = lane < 8 ? wB[lane] : 0.f;
#pragma unroll
        for (int off = 4; off > 0; off >>= 1) {
            vN += __shfl_down_sync(0xffffffffu, vN, off);
            vD += __shfl_down_sync(0xffffffffu, vD, off);
            vB += __shfl_down_sync(0xffffffffu, vB, off);
        }
        if (lane == 0) {
            g_part[3 * blockIdx.x + 0] = vN;
            g_part[3 * blockIdx.x + 1] = vD;
            g_part[3 * blockIdx.x + 2] = vB;
        }
    }

    __threadfence();
    if (tid == 0) {
        unsigned prev = atomicAdd(&g_count, 1u);
        is_last = (prev == B_BLOCKS - 1);
    }
    __syncthreads();
    if (!is_last) return;

    double sN = 0.0, sD = 0.0, sB = 0.0;
    for (int b = tid; b < B_BLOCKS; b += 256) {
        sN += (double)g_part[3 * b + 0];
        sD += (double)g_part[3 * b + 1];
        sB += (double)g_part[3 * b + 2];
    }
    __shared__ double rd[256];
    rd[tid] = sN; __syncthreads();
    for (int s = 128; s > 0; s >>= 1) { if (tid < s) rd[tid] += rd[tid + s]; __syncthreads(); }
    double tN = rd[0]; __syncthreads();
    rd[tid] = sD; __syncthreads();
    for (int s = 128; s > 0; s >>= 1) { if (tid < s) rd[tid] += rd[tid + s]; __syncthreads(); }
    double tD = rd[0]; __syncthreads();
    rd[tid] = sB; __syncthreads();
    for (int s = 128; s > 0; s >>= 1) { if (tid < s) rd[tid] += rd[tid + s]; __syncthreads(); }
    double tB = rd[0];

    if (tid == 0) {
        double dice = 1.0 - (2.0 * tN + 1e-3) / (tD + 1e-3);
        double vol = tB / (8.0 * NP_WIN);
        out[0] = (float)(dice + vol);
    }
}

// ---------------------------------------------------------------------------
extern "C" void kernel_launch(void* const* d_in, const int* in_sizes, int n_in,
                              void* d_out, int out_size) {
    const float* pred   = (const float*)d_in[0];
    const int*   labels = (const int*)d_in[1];
    const float* area   = (const float*)d_in[2];

    k1<<<YD, XD>>>(pred, labels);
    k2<<<B_BLOCKS, 256>>>(pred, area, (float*)d_out);
}